// round 14
// baseline (speedup 1.0000x reference)
#include <cuda_runtime.h>
#include <cuda_bf16.h>
#include <cuda_fp16.h>
#include <cstdint>

#define BB 8
#define LL 1024
#define DM 256
#define DI 512
#define DS 16
#define NT (BB*LL)   // 8192 tokens
#define NDTBC 576    // 512 dt + 16 B + 16 C + 32 pad
#define NTDI ((size_t)NT*DI)

// ---------------- scratch (device globals: allocation-free) ----------------
__device__ float g_h [NT*DM];
__device__ float g_bc[NT*32];        // B|C per token (fp32)
__device__ float g_sdt[NT*DI];       // softplus(dt_pre)
__device__ __half g_szh[NT*DI];      // silu(z) fp16 (inproj epilogue)
__device__ __half2 g_szdxz[NT*DI];   // (silu(z), D*x*silu(z)) packed
__device__ __half g_x [NT*DI];       // pre-conv x (inproj epilogue)
__device__ __half g_a [NT*DI];       // LN out (256-stride) / conv out (512-stride)
__device__ __half g_y [NT*DI];       // scan out
__device__ __half g_win_h [4*1024*256];
__device__ __half g_win_l [4*1024*256];
__device__ __half g_wdt_h [4*NDTBC*512];   // rows 544..575 stay zero
__device__ __half g_wdt_l [4*NDTBC*512];
__device__ __half g_wout_h[4*256*512];
__device__ __half g_wout_l[4*256*512];
__device__ float g_bias[4*NDTBC];

// ---------------- helpers ----------------
__device__ __forceinline__ uint32_t smem_u32(const void* p) {
    uint32_t a;
    asm("{ .reg .u64 t; cvta.to.shared.u64 t, %1; cvt.u32.u64 %0, t; }" : "=r"(a) : "l"(p));
    return a;
}
__device__ __forceinline__ void ldsm4(uint32_t* r, uint32_t addr) {
    asm volatile("ldmatrix.sync.aligned.m8n8.x4.shared.b16 {%0,%1,%2,%3}, [%4];"
                 : "=r"(r[0]), "=r"(r[1]), "=r"(r[2]), "=r"(r[3]) : "r"(addr));
}
__device__ __forceinline__ void ldsm2(uint32_t* r, uint32_t addr) {
    asm volatile("ldmatrix.sync.aligned.m8n8.x2.shared.b16 {%0,%1}, [%2];"
                 : "=r"(r[0]), "=r"(r[1]) : "r"(addr));
}
__device__ __forceinline__ void mma_f16(float* c, const uint32_t* a, const uint32_t* b) {
    asm volatile("mma.sync.aligned.m16n8k16.row.col.f32.f16.f16.f32 "
        "{%0,%1,%2,%3}, {%4,%5,%6,%7}, {%8,%9}, {%0,%1,%2,%3};"
        : "+f"(c[0]), "+f"(c[1]), "+f"(c[2]), "+f"(c[3])
        : "r"(a[0]), "r"(a[1]), "r"(a[2]), "r"(a[3]), "r"(b[0]), "r"(b[1]));
}
__device__ __forceinline__ void cp16(uint32_t dst, const void* src) {
    asm volatile("cp.async.cg.shared.global [%0], [%1], 16;" :: "r"(dst), "l"(src));
}
#define CP_COMMIT() asm volatile("cp.async.commit_group;" ::: "memory")
#define CP_WAIT1()  asm volatile("cp.async.wait_group 1;" ::: "memory")
__device__ __forceinline__ float ex2f(float x) {
    float r; asm("ex2.approx.f32 %0, %1;" : "=f"(r) : "f"(x)); return r;
}

#define PITCH 40   // fp16 elems per smem row (80B), BK=32, conflict-free ldmatrix
#define ST_ELEMS ((128 + 64 + 64) * PITCH)   // 10240 elems / stage
#define SM_A  0
#define SM_WH (128*PITCH)
#define SM_WL (192*PITCH)
#define GEMM_SMEM (3*ST_ELEMS*2)             // 61440 B -> 3 CTAs/SM

// ---------------- tensor-core GEMM: CTA tile 128x64, warp tile 32x32 -------
// A single fp16 [M][K]; W fp16 hi/lo [Npad][K]. 2-term: A*Wh + A*Wl.
// modes: 0 = store C, 1 = accumulate into C, 2 = dtbc epilogue,
//        3 = inproj epilogue (x -> fp16, z -> silu fp16)
__device__ __forceinline__ void load_chunk(
    uint32_t base, const __half* A, const __half* Wh, const __half* Wl,
    int mBase, int nBase, int K, int k0, int tid)
{
    #pragma unroll
    for (int i = 0; i < 2; i++) {
        int idx = tid + i*256;                 // 0..511: 128 rows x 4 segs
        int row = idx >> 2, seg = (idx & 3) << 3;
        size_t go = (size_t)(mBase + row)*K + k0 + seg;
        cp16(base + SM_A*2 + (uint32_t)(row*PITCH + seg)*2, A + go);
    }
    {
        int row = tid >> 2, seg = (tid & 3) << 3;  // 64 rows x 4 segs
        size_t go = (size_t)(nBase + row)*K + k0 + seg;
        uint32_t so = (uint32_t)(row*PITCH + seg)*2;
        cp16(base + SM_WH*2 + so, Wh + go);
        cp16(base + SM_WL*2 + so, Wl + go);
    }
}

__device__ __forceinline__ void dtbc_pair(int t, int gn, float v0, float v1,
                                          float* sdt, float* bc) {
    if (gn < 512) {
        float d0 = (v0 > 20.f) ? v0 : __logf(1.f + __expf(v0));
        float d1 = (v1 > 20.f) ? v1 : __logf(1.f + __expf(v1));
        *(float2*)(sdt + (size_t)t*DI + gn) = make_float2(d0, d1);
    } else if (gn < 544) {
        *(float2*)(bc + (size_t)t*32 + (gn - 512)) = make_float2(v0, v1);
    }
}
__device__ __forceinline__ void inproj_pair(int t, int gn, float v0, float v1,
                                            __half* gx, __half* szh) {
    if (gn < 512) {
        *(__half2*)(gx + (size_t)t*DI + gn) = __floats2half2_rn(v0, v1);
    } else {
        float s0 = v0 / (1.f + __expf(-v0));
        float s1 = v1 / (1.f + __expf(-v1));
        *(__half2*)(szh + (size_t)t*DI + (gn - 512)) = __floats2half2_rn(s0, s1);
    }
}

__global__ void __launch_bounds__(256, 3) k_tcgemm(
    const __half* __restrict__ A,
    const __half* __restrict__ Wh, const __half* __restrict__ Wl,
    const float* __restrict__ bias, float* __restrict__ C,
    int K, int ldc, int Nstore, int mode,
    float* __restrict__ p0, float* __restrict__ p1)
{
    extern __shared__ __half smem[];
    uint32_t sb = smem_u32(smem);

    int tid = threadIdx.x, lane = tid & 31, warp = tid >> 5;
    int mBase = blockIdx.y * 128, nBase = blockIdx.x * 64;
    int mw = (warp & 3) * 32;
    int nw = (warp >> 2) * 32;

    float acc[2][4][4];
    #pragma unroll
    for (int i = 0; i < 2; i++)
        #pragma unroll
        for (int j = 0; j < 4; j++)
            #pragma unroll
            for (int k = 0; k < 4; k++) acc[i][j][k] = 0.f;

    int arow = mw + (lane & 15);
    int acolH = (lane >> 4) << 3;
    int brow = nw + (lane & 7);
    int bcolH = (lane & 8);

    int nch = K >> 5;
    load_chunk(sb, A, Wh, Wl, mBase, nBase, K, 0, tid);
    CP_COMMIT();
    load_chunk(sb + ST_ELEMS*2, A, Wh, Wl, mBase, nBase, K, 32, tid);
    CP_COMMIT();

    for (int c = 0; c < nch; c++) {
        CP_WAIT1();
        __syncthreads();
        uint32_t b0 = sb + (c % 3)*(ST_ELEMS*2);
        #pragma unroll
        for (int ks = 0; ks < 32; ks += 16) {
            uint32_t a[2][4], bh[4][2], bl[4][2];
            ldsm4(a[0], b0 + (uint32_t)(SM_A + (arow     )*PITCH + ks + acolH)*2);
            ldsm4(a[1], b0 + (uint32_t)(SM_A + (arow + 16)*PITCH + ks + acolH)*2);
            #pragma unroll
            for (int ni = 0; ni < 4; ni++) {
                uint32_t wo = (uint32_t)((brow + ni*8)*PITCH + ks + bcolH)*2;
                ldsm2(bh[ni], b0 + SM_WH*2 + wo);
                ldsm2(bl[ni], b0 + SM_WL*2 + wo);
            }
            #pragma unroll
            for (int mi = 0; mi < 2; mi++)
                #pragma unroll
                for (int ni = 0; ni < 4; ni++) {
                    mma_f16(acc[mi][ni], a[mi], bh[ni]);
                    mma_f16(acc[mi][ni], a[mi], bl[ni]);
                }
        }
        if (c + 2 < nch)
            load_chunk(sb + ((c + 2) % 3)*(ST_ELEMS*2), A, Wh, Wl,
                       mBase, nBase, K, (c + 2)*32, tid);
        CP_COMMIT();
    }

    int cr = lane >> 2, cc = (lane & 3) * 2;
    #pragma unroll
    for (int mi = 0; mi < 2; mi++) {
        #pragma unroll
        for (int ni = 0; ni < 4; ni++) {
            int gn = nBase + nw + ni*8 + cc;
            int row0 = mBase + mw + mi*16 + cr;
            if (mode == 3) {
                inproj_pair(row0,     gn, acc[mi][ni][0], acc[mi][ni][1],
                            (__half*)p0, (__half*)p1);
                inproj_pair(row0 + 8, gn, acc[mi][ni][2], acc[mi][ni][3],
                            (__half*)p0, (__half*)p1);
            } else if (mode == 2) {
                float b0v = bias[gn], b1v = bias[gn + 1];
                dtbc_pair(row0,     gn, acc[mi][ni][0] + b0v, acc[mi][ni][1] + b1v, p0, p1);
                dtbc_pair(row0 + 8, gn, acc[mi][ni][2] + b0v, acc[mi][ni][3] + b1v, p0, p1);
            } else {
                if (gn >= Nstore) continue;
                float* pc0 = C + (size_t)row0*ldc + gn;
                float* pc1 = C + (size_t)(row0 + 8)*ldc + gn;
                float2 v0 = make_float2(acc[mi][ni][0], acc[mi][ni][1]);
                float2 v1 = make_float2(acc[mi][ni][2], acc[mi][ni][3]);
                if (mode == 1) {
                    float2 o0 = *(float2*)pc0, o1 = *(float2*)pc1;
                    v0.x += o0.x; v0.y += o0.y; v1.x += o1.x; v1.y += o1.y;
                }
                *(float2*)pc0 = v0;
                *(float2*)pc1 = v1;
            }
        }
    }
}

// ---------------- weight prep: transpose + fp16 hi/lo split ----------------
__global__ void k_tr(const float* __restrict__ src, __half* __restrict__ dh,
                     __half* __restrict__ dl, int K, int N,
                     size_t sLayer, size_t dLayer) {
    __shared__ float tile[32][33];
    const float* s = src + blockIdx.z * sLayer;
    size_t doff = blockIdx.z * dLayer;
    int n0 = blockIdx.x * 32, k0 = blockIdx.y * 32;
    int tx = threadIdx.x, ty = threadIdx.y;
    #pragma unroll
    for (int i = 0; i < 4; i++)
        tile[ty + i*8][tx] = s[(size_t)(k0 + ty + i*8)*N + n0 + tx];
    __syncthreads();
    #pragma unroll
    for (int i = 0; i < 4; i++) {
        float v = tile[tx][ty + i*8];
        size_t o = doff + (size_t)(n0 + ty + i*8)*K + k0 + tx;
        __half hh = __float2half(v);
        dh[o] = hh;
        dl[o] = __float2half(v - __half2float(hh));
    }
}
__global__ void k_prep_bc(const float* __restrict__ WB, const float* __restrict__ WC,
                          const float* __restrict__ bdt,
                          __half* __restrict__ Wh, __half* __restrict__ Wl,
                          float* __restrict__ bias) {
    int idx = blockIdx.x * 256 + threadIdx.x;   // 4*512*32
    int l = idx >> 14, r = idx & 16383, k = r >> 5, c = r & 31;
    float v = (c < 16) ? WB[((size_t)l*512 + k)*16 + c]
                       : WC[((size_t)l*512 + k)*16 + (c - 16)];
    size_t o = ((size_t)l*NDTBC + 512 + c)*512 + k;
    __half hh = __float2half(v);
    Wh[o] = hh;
    Wl[o] = __float2half(v - __half2float(hh));
    if (idx < 4*NDTBC) {
        int ll = idx / NDTBC, n = idx % NDTBC;
        bias[idx] = (n < 512) ? bdt[ll*512 + n] : 0.f;
    }
}

// ---------------- non-GEMM kernels ----------------
__device__ __forceinline__ float blkSum128(float v) {
    __shared__ float sh[4];
    v += __shfl_xor_sync(0xffffffffu, v, 16);
    v += __shfl_xor_sync(0xffffffffu, v, 8);
    v += __shfl_xor_sync(0xffffffffu, v, 4);
    v += __shfl_xor_sync(0xffffffffu, v, 2);
    v += __shfl_xor_sync(0xffffffffu, v, 1);
    __syncthreads();
    if ((threadIdx.x & 31) == 0) sh[threadIdx.x >> 5] = v;
    __syncthreads();
    return sh[0]+sh[1]+sh[2]+sh[3];
}
__device__ __forceinline__ float blkSum256(float v) {
    __shared__ float sh[8];
    v += __shfl_xor_sync(0xffffffffu, v, 16);
    v += __shfl_xor_sync(0xffffffffu, v, 8);
    v += __shfl_xor_sync(0xffffffffu, v, 4);
    v += __shfl_xor_sync(0xffffffffu, v, 2);
    v += __shfl_xor_sync(0xffffffffu, v, 1);
    __syncthreads();
    if ((threadIdx.x & 31) == 0) sh[threadIdx.x >> 5] = v;
    __syncthreads();
    return sh[0]+sh[1]+sh[2]+sh[3]+sh[4]+sh[5]+sh[6]+sh[7];
}
__global__ void k_inproj_ln2(const float* __restrict__ x, const float* __restrict__ w_in,
                             const float* __restrict__ b_in, const float* __restrict__ g0,
                             const float* __restrict__ be0, const float* __restrict__ g1,
                             const float* __restrict__ be1, float* __restrict__ out,
                             __half* __restrict__ oa) {
    int t = blockIdx.x, d2 = threadIdx.x * 2;
    int b = t >> 10, l = t & 1023;
    const float* xb = x + (size_t)b*4*LL + l;
    float xc[4];
    #pragma unroll
    for (int c = 0; c < 4; c++) xc[c] = xb[c*LL];
    float v0 = b_in[d2], v1 = b_in[d2 + 1];
    #pragma unroll
    for (int c = 0; c < 4; c++) {
        v0 += xc[c] * w_in[d2*4 + c];
        v1 += xc[c] * w_in[(d2+1)*4 + c];
    }
    float mean = blkSum128(v0 + v1) * (1.f/DM);
    float e0 = v0 - mean, e1 = v1 - mean;
    float var = blkSum128(e0*e0 + e1*e1) * (1.f/DM);
    float rs = rsqrtf(var + 1e-5f);
    float u0 = e0*rs*g0[d2] + be0[d2];
    float u1 = e1*rs*g0[d2+1] + be0[d2+1];
    *(float2*)(out + (size_t)t*DM + d2) = make_float2(u0, u1);
    float m2 = blkSum128(u0 + u1) * (1.f/DM);
    float f0 = u0 - m2, f1 = u1 - m2;
    float v2 = blkSum128(f0*f0 + f1*f1) * (1.f/DM);
    float rs2 = rsqrtf(v2 + 1e-5f);
    *(__half2*)(oa + (size_t)t*DM + d2) =
        __floats2half2_rn(f0*rs2*g1[d2] + be1[d2], f1*rs2*g1[d2+1] + be1[d2+1]);
}
__global__ void k_ln_split(const float* __restrict__ src, const float* __restrict__ g,
                           const float* __restrict__ be, __half* __restrict__ oa) {
    int t = blockIdx.x, d2 = threadIdx.x * 2;
    float2 v = *(const float2*)(src + (size_t)t*DM + d2);
    float mean = blkSum128(v.x + v.y) * (1.f/DM);
    float e0 = v.x - mean, e1 = v.y - mean;
    float var = blkSum128(e0*e0 + e1*e1) * (1.f/DM);
    float rs = rsqrtf(var + 1e-5f);
    *(__half2*)(oa + (size_t)t*DM + d2) =
        __floats2half2_rn(e0*rs*g[d2] + be[d2], e1*rs*g[d2+1] + be[d2+1]);
}
__global__ void k_lnmean(const float* __restrict__ src, const float* __restrict__ g,
                         const float* __restrict__ be, float* __restrict__ out) {
    int t = blockIdx.x, d = threadIdx.x;
    float v = src[(size_t)t*DM + d];
    float mean = blkSum256(v) * (1.f/DM);
    float diff = v - mean;
    float var  = blkSum256(diff*diff) * (1.f/DM);
    float r = diff * rsqrtf(var + 1e-5f) * g[d] + be[d];
    atomicAdd(out + (t >> 10)*DM + d, r * (1.f/LL));
}
// conv + silu, 2 adjacent d per thread; fp16 in, fp16 out
__global__ void k_conv(const __half* __restrict__ gx, const __half* __restrict__ szh,
                       const float* __restrict__ cw, const float* __restrict__ cb,
                       const float* __restrict__ Dv,
                       __half* __restrict__ oa, __half2* __restrict__ szdxz) {
    int idx2 = blockIdx.x * blockDim.x + threadIdx.x;   // over NT*DI/2
    int d2 = (idx2 & (DI/2 - 1)) * 2;
    int t = idx2 >> 8;
    int l = t & (LL - 1);
    size_t base = (size_t)t*DI + d2;
    float acc0 = cb[d2], acc1 = cb[d2 + 1];
    #pragma unroll
    for (int j = 0; j < 4; j++) {
        int ls = l - 3 + j;
        if (ls >= 0) {
            __half2 x2 = *(const __half2*)(gx + base + (size_t)(j - 3)*DI);
            acc0 += __half2float(x2.x) * cw[d2*4 + j];
            acc1 += __half2float(x2.y) * cw[(d2+1)*4 + j];
        }
    }
    float r0 = acc0 / (1.f + __expf(-acc0));
    float r1 = acc1 / (1.f + __expf(-acc1));
    *(__half2*)(oa + base) = __floats2half2_rn(r0, r1);
    __half2 z2 = *(const __half2*)(szh + base);
    float s0 = __half2float(z2.x), s1 = __half2float(z2.y);
    __half2 g0 = __floats2half2_rn(s0, Dv[d2] * r0 * s0);
    __half2 g1 = __floats2half2_rn(s1, Dv[d2+1] * r1 * s1);
    uint2 pk;
    pk.x = *(uint32_t*)&g0;
    pk.y = *(uint32_t*)&g1;
    *(uint2*)(szdxz + base) = pk;
}

// ---------------- selective scan: chunked-parallel (64-token warmup) -------
// record/token (words): dt[0,16) | x fp16 [16,24) | B[24,40) | C[40,56) | g half2 [56,72)
#define SC_TOK 72
#define SC_TILE 64
#define SC_EMIT 256
#define SC_BUF (SC_TILE*SC_TOK)
#define SCAN_SMEM (2*SC_BUF*4)

__device__ __forceinline__ void scan_load_tile(
    uint32_t sdst, int tok0, int dbase, int tid,
    const float* sdt, const __half* xa, const float* bc, const __half2* szdxz)
{
    int token = tid >> 2, q = tid & 3;
    int t = tok0 + token;
    uint32_t dst = sdst + (uint32_t)(token*SC_TOK)*4;
    size_t o512 = (size_t)t*DI + dbase;
    cp16(dst +       q*16, sdt + o512 + q*4);
    if (q < 2) cp16(dst + 64 + q*16, xa + o512 + q*8);
    cp16(dst +  96 + q*16, bc + (size_t)t*32 + q*4);
    cp16(dst + 160 + q*16, bc + (size_t)t*32 + 16 + q*4);
    cp16(dst + 224 + q*16, szdxz + o512 + q*4);
}

__global__ void __launch_bounds__(256) k_scan(
    const float* __restrict__ sdt, const float* __restrict__ bc,
    const __half2* __restrict__ szdxz, const float* __restrict__ A_log,
    const __half* __restrict__ xa, __half* __restrict__ y)
{
    extern __shared__ float sbuf[];
    uint32_t sbase = smem_u32(sbuf);
    int tid = threadIdx.x, warp = tid >> 5, lane = tid & 31;
    int b     = blockIdx.x >> 5;
    int dbase = (blockIdx.x & 31) * 16;
    int chunk = blockIdx.y;
    int half = lane >> 4, s = lane & 15;
    int dloc = warp*2 + half;
    int d = dbase + dloc;
    const int tb = b * LL;

    int emit0 = chunk * SC_EMIT;
    int start = (chunk == 0) ? 0 : emit0 - SC_TILE;
    int warmTiles = (chunk == 0) ? 0 : 1;
    int ntiles = (emit0 + SC_EMIT - start) / SC_TILE;

    float A2 = -__expf(A_log[d*DS + s]) * 1.4426950408889634f;
    float h = 0.f;

    scan_load_tile(sbase, tb + start, dbase, tid, sdt, xa, bc, szdxz);
    CP_COMMIT();
    scan_load_tile(sbase + SC_BUF*4, tb + start + SC_TILE, dbase, tid,
                   sdt, xa, bc, szdxz);
    CP_COMMIT();

    for (int tile = 0; tile < ntiles; tile++) {
        CP_WAIT1();
        __syncthreads();
        const float* buf = sbuf + (tile & 1) * SC_BUF;
        int t0 = tb + start + tile*SC_TILE;
        bool emit = (tile >= warmTiles);
        #pragma unroll 4
        for (int k = 0; k < SC_TILE; k++) {
            const float* rec = buf + k*SC_TOK;
            const __half* xp = (const __half*)(rec + 16);
            float dtv = rec[dloc];
            float xv  = __half2float(xp[dloc]);
            float Bv  = rec[24 + s];
            float Cv  = rec[40 + s];
            float Ab = ex2f(A2 * dtv);
            h = Ab * h + (dtv * xv) * Bv;
            float p = h * Cv;
            p += __shfl_xor_sync(0xffffffffu, p, 8);
            p += __shfl_xor_sync(0xffffffffu, p, 4);
            p += __shfl_xor_sync(0xffffffffu, p, 2);
            p += __shfl_xor_sync(0xffffffffu, p, 1);
            if (emit && s == 0) {
                float2 gv = __half22float2(((const __half2*)(rec + 56))[dloc]);
                y[(size_t)(t0 + k)*DI + d] = __float2half(p * gv.x + gv.y);
            }
        }
        __syncthreads();
        if (tile + 2 < ntiles)
            scan_load_tile(sbase + (tile & 1)*SC_BUF*4,
                           tb + start + (tile + 2)*SC_TILE, dbase, tid,
                           sdt, xa, bc, szdxz);
        CP_COMMIT();
    }
}

__global__ void k_zero(float* __restrict__ out) {
    out[blockIdx.x * DM + threadIdx.x] = 0.f;
}

// ---------------- host ----------------
extern "C" void kernel_launch(void* const* d_in, const int* in_sizes, int n_in,
                              void* d_out, int out_size) {
    const float* x       = (const float*)d_in[0];
    const float* w_in    = (const float*)d_in[1];
    const float* b_in    = (const float*)d_in[2];
    const float* ln_in_g = (const float*)d_in[3];
    const float* ln_in_b = (const float*)d_in[4];
    const float* ln_g    = (const float*)d_in[5];
    const float* ln_b    = (const float*)d_in[6];
    const float* W_inpr  = (const float*)d_in[7];
    const float* conv_w  = (const float*)d_in[8];
    const float* conv_b  = (const float*)d_in[9];
    const float* W_dt    = (const float*)d_in[10];
    const float* b_dt    = (const float*)d_in[11];
    const float* W_B     = (const float*)d_in[12];
    const float* W_C     = (const float*)d_in[13];
    const float* A_log   = (const float*)d_in[14];
    const float* Dv      = (const float*)d_in[15];
    const float* W_out   = (const float*)d_in[16];
    const float* ln_f_g  = (const float*)d_in[17];
    const float* ln_f_b  = (const float*)d_in[18];
    float* out = (float*)d_out;

    float *h, *bias, *bcv, *sdt;
    __half *szh, *gx, *ga, *gy;
    __half2* szdxz;
    __half *winh, *winl, *wdth, *wdtl, *wouth, *woutl;
    cudaGetSymbolAddress((void**)&h,     g_h);
    cudaGetSymbolAddress((void**)&bcv,   g_bc);
    cudaGetSymbolAddress((void**)&sdt,   g_sdt);
    cudaGetSymbolAddress((void**)&szh,   g_szh);
    cudaGetSymbolAddress((void**)&szdxz, g_szdxz);
    cudaGetSymbolAddress((void**)&gx,    g_x);
    cudaGetSymbolAddress((void**)&ga,    g_a);
    cudaGetSymbolAddress((void**)&gy,    g_y);
    cudaGetSymbolAddress((void**)&bias,  g_bias);
    cudaGetSymbolAddress((void**)&winh,  g_win_h);
    cudaGetSymbolAddress((void**)&winl,  g_win_l);
    cudaGetSymbolAddress((void**)&wdth,  g_wdt_h);
    cudaGetSymbolAddress((void**)&wdtl,  g_wdt_l);
    cudaGetSymbolAddress((void**)&wouth, g_wout_h);
    cudaGetSymbolAddress((void**)&woutl, g_wout_l);

    cudaFuncSetAttribute(k_tcgemm, cudaFuncAttributeMaxDynamicSharedMemorySize, GEMM_SMEM);
    cudaFuncSetAttribute(k_scan,   cudaFuncAttributeMaxDynamicSharedMemorySize, SCAN_SMEM);

    dim3 trb(32, 8);
    k_tr<<<dim3(32, 8, 4), trb>>>(W_inpr, winh, winl, 256, 1024,                 // 0
                                  (size_t)256*1024, (size_t)1024*256);
    k_tr<<<dim3(16, 16, 4), trb>>>(W_dt, wdth, wdtl, 512, 512,                   // 1
                                   (size_t)512*512, (size_t)NDTBC*512);
    k_inproj_ln2<<<NT, 128>>>(x, w_in, b_in, ln_in_g, ln_in_b,                   // 2
                              ln_g, ln_b, h, ga);
    k_tcgemm<<<dim3(16, 64), 256, GEMM_SMEM>>>(                                  // 3 <- prof
        ga, winh, winl, nullptr, nullptr, 256, 0, 0, 3, (float*)gx, (float*)szh);
    k_prep_bc<<<(4*512*32)/256, 256>>>(W_B, W_C, b_dt, wdth, wdtl, bias);
    k_tr<<<dim3(8, 16, 4), trb>>>(W_out, wouth, woutl, 512, 256,
                                  (size_t)512*256, (size_t)256*512);

    for (int i = 0; i < 4; i++) {
        if (i > 0) {
            k_ln_split<<<NT, 128>>>(h, ln_g + i*DM, ln_b + i*DM, ga);
            k_tcgemm<<<dim3(16, 64), 256, GEMM_SMEM>>>(
                ga, winh + (size_t)i*1024*256, winl + (size_t)i*1024*256,
                nullptr, nullptr, 256, 0, 0, 3, (float*)gx, (float*)szh);
        }
        k_conv<<<(NT*DI/2)/256, 256>>>(gx, szh, conv_w + i*DI*4, conv_b + i*DI,
                                       Dv + i*DI, ga, szdxz);
        k_tcgemm<<<dim3(NDTBC/64, 64), 256, GEMM_SMEM>>>(
            ga, wdth + (size_t)i*NDTBC*512, wdtl + (size_t)i*NDTBC*512,
            bias + i*NDTBC, nullptr, 512, 0, 0, 2, sdt, bcv);
        k_scan<<<dim3(BB*(DI/16), LL/SC_EMIT), 256, SCAN_SMEM>>>(
            sdt, bcv, szdxz, A_log + i*DI*DS, ga, gy);
        k_tcgemm<<<dim3(4, 64), 256, GEMM_SMEM>>>(
            gy, wouth + (size_t)i*256*512, woutl + (size_t)i*256*512,
            nullptr, h, 512, 256, 256, 1, nullptr, nullptr);
    }

    k_zero<<<BB, DM>>>(out);
    k_lnmean<<<NT, 256>>>(h, ln_f_g, ln_f_b, out);
}

// round 15
// speedup vs baseline: 1.5929x; 1.5929x over previous
#include <cuda_runtime.h>
#include <cuda_bf16.h>
#include <cuda_fp16.h>
#include <cstdint>

#define BB 8
#define LL 1024
#define DM 256
#define DI 512
#define DS 16
#define NT (BB*LL)   // 8192 tokens
#define NDTBC 576    // 512 dt + 16 B + 16 C + 32 pad
#define NTDI ((size_t)NT*DI)

// ---------------- scratch (device globals: allocation-free) ----------------
__device__ float g_h [NT*DM];
__device__ float g_bc[NT*32];        // B|C per token (fp32)
__device__ float g_sdt[NT*DI];       // softplus(dt_pre)
__device__ __half g_szh[NT*DI];      // silu(z) fp16 (inproj epilogue)
__device__ __half2 g_szdxz[NT*DI];   // (silu(z), D*x*silu(z)) packed
__device__ __half g_x [NT*DI];       // pre-conv x (inproj epilogue, conv input only)
__device__ __nv_bfloat16 g_a [NT*DI];   // GEMM A: LN out (256-stride) / conv out (512)
__device__ __nv_bfloat16 g_y [NT*DI];   // scan out (GEMM A for out-proj)
__device__ __nv_bfloat16 g_win_h [4*1024*256];
__device__ __nv_bfloat16 g_win_l [4*1024*256];
__device__ __nv_bfloat16 g_wdt_h [4*NDTBC*512];   // rows 544..575 stay zero
__device__ __nv_bfloat16 g_wdt_l [4*NDTBC*512];
__device__ __nv_bfloat16 g_wout_h[4*256*512];
__device__ __nv_bfloat16 g_wout_l[4*256*512];
__device__ float g_bias[4*NDTBC];

// ---------------- helpers ----------------
__device__ __forceinline__ uint32_t smem_u32(const void* p) {
    uint32_t a;
    asm("{ .reg .u64 t; cvta.to.shared.u64 t, %1; cvt.u32.u64 %0, t; }" : "=r"(a) : "l"(p));
    return a;
}
__device__ __forceinline__ void ldsm4(uint32_t* r, uint32_t addr) {
    asm volatile("ldmatrix.sync.aligned.m8n8.x4.shared.b16 {%0,%1,%2,%3}, [%4];"
                 : "=r"(r[0]), "=r"(r[1]), "=r"(r[2]), "=r"(r[3]) : "r"(addr));
}
__device__ __forceinline__ void ldsm2(uint32_t* r, uint32_t addr) {
    asm volatile("ldmatrix.sync.aligned.m8n8.x2.shared.b16 {%0,%1}, [%2];"
                 : "=r"(r[0]), "=r"(r[1]) : "r"(addr));
}
__device__ __forceinline__ void mma_bf16(float* c, const uint32_t* a, const uint32_t* b) {
    asm volatile("mma.sync.aligned.m16n8k16.row.col.f32.bf16.bf16.f32 "
        "{%0,%1,%2,%3}, {%4,%5,%6,%7}, {%8,%9}, {%0,%1,%2,%3};"
        : "+f"(c[0]), "+f"(c[1]), "+f"(c[2]), "+f"(c[3])
        : "r"(a[0]), "r"(a[1]), "r"(a[2]), "r"(a[3]), "r"(b[0]), "r"(b[1]));
}
__device__ __forceinline__ void cp16(uint32_t dst, const void* src) {
    asm volatile("cp.async.cg.shared.global [%0], [%1], 16;" :: "r"(dst), "l"(src));
}
#define CP_COMMIT() asm volatile("cp.async.commit_group;" ::: "memory")
#define CP_WAIT1()  asm volatile("cp.async.wait_group 1;" ::: "memory")
__device__ __forceinline__ float ex2f(float x) {
    float r; asm("ex2.approx.f32 %0, %1;" : "=f"(r) : "f"(x)); return r;
}

#define PITCH 40   // bf16 elems per smem row (80B), BK=32, conflict-free ldmatrix
#define ST_ELEMS ((128 + 64 + 64) * PITCH)   // 10240 elems / stage
#define SM_A  0
#define SM_WH (128*PITCH)
#define SM_WL (192*PITCH)
#define GEMM_SMEM (3*ST_ELEMS*2)             // 61440 B -> 3 CTAs/SM

// ---------------- tensor-core GEMM: CTA tile 128x64, warp tile 32x32 -------
// A single bf16 [M][K]; W bf16 hi/lo [Npad][K]. 2-term: A*Wh + A*Wl.
// modes: 0 = store C, 1 = accumulate into C, 2 = dtbc epilogue,
//        3 = inproj epilogue (x -> fp16, z -> silu fp16)
__device__ __forceinline__ void load_chunk(
    uint32_t base, const __nv_bfloat16* A,
    const __nv_bfloat16* Wh, const __nv_bfloat16* Wl,
    int mBase, int nBase, int K, int k0, int tid)
{
    #pragma unroll
    for (int i = 0; i < 2; i++) {
        int idx = tid + i*256;                 // 0..511: 128 rows x 4 segs
        int row = idx >> 2, seg = (idx & 3) << 3;
        size_t go = (size_t)(mBase + row)*K + k0 + seg;
        cp16(base + SM_A*2 + (uint32_t)(row*PITCH + seg)*2, A + go);
    }
    {
        int row = tid >> 2, seg = (tid & 3) << 3;  // 64 rows x 4 segs
        size_t go = (size_t)(nBase + row)*K + k0 + seg;
        uint32_t so = (uint32_t)(row*PITCH + seg)*2;
        cp16(base + SM_WH*2 + so, Wh + go);
        cp16(base + SM_WL*2 + so, Wl + go);
    }
}

__device__ __forceinline__ void dtbc_pair(int t, int gn, float v0, float v1,
                                          float* sdt, float* bc) {
    if (gn < 512) {
        float d0 = (v0 > 20.f) ? v0 : __logf(1.f + __expf(v0));
        float d1 = (v1 > 20.f) ? v1 : __logf(1.f + __expf(v1));
        *(float2*)(sdt + (size_t)t*DI + gn) = make_float2(d0, d1);
    } else if (gn < 544) {
        *(float2*)(bc + (size_t)t*32 + (gn - 512)) = make_float2(v0, v1);
    }
}
__device__ __forceinline__ void inproj_pair(int t, int gn, float v0, float v1,
                                            __half* gx, __half* szh) {
    if (gn < 512) {
        *(__half2*)(gx + (size_t)t*DI + gn) = __floats2half2_rn(v0, v1);
    } else {
        float s0 = v0 / (1.f + __expf(-v0));
        float s1 = v1 / (1.f + __expf(-v1));
        *(__half2*)(szh + (size_t)t*DI + (gn - 512)) = __floats2half2_rn(s0, s1);
    }
}

__global__ void __launch_bounds__(256, 3) k_tcgemm(
    const __nv_bfloat16* __restrict__ A,
    const __nv_bfloat16* __restrict__ Wh, const __nv_bfloat16* __restrict__ Wl,
    const float* __restrict__ bias, float* __restrict__ C,
    int K, int ldc, int Nstore, int mode,
    float* __restrict__ p0, float* __restrict__ p1)
{
    extern __shared__ __nv_bfloat16 smem[];
    uint32_t sb = smem_u32(smem);

    int tid = threadIdx.x, lane = tid & 31, warp = tid >> 5;
    int mBase = blockIdx.y * 128, nBase = blockIdx.x * 64;
    int mw = (warp & 3) * 32;
    int nw = (warp >> 2) * 32;

    float acc[2][4][4];
    #pragma unroll
    for (int i = 0; i < 2; i++)
        #pragma unroll
        for (int j = 0; j < 4; j++)
            #pragma unroll
            for (int k = 0; k < 4; k++) acc[i][j][k] = 0.f;

    int arow = mw + (lane & 15);
    int acolH = (lane >> 4) << 3;
    int brow = nw + (lane & 7);
    int bcolH = (lane & 8);

    int nch = K >> 5;
    load_chunk(sb, A, Wh, Wl, mBase, nBase, K, 0, tid);
    CP_COMMIT();
    load_chunk(sb + ST_ELEMS*2, A, Wh, Wl, mBase, nBase, K, 32, tid);
    CP_COMMIT();

    for (int c = 0; c < nch; c++) {
        CP_WAIT1();
        __syncthreads();
        uint32_t b0 = sb + (c % 3)*(ST_ELEMS*2);
        #pragma unroll
        for (int ks = 0; ks < 32; ks += 16) {
            uint32_t a[2][4], bh[4][2], bl[4][2];
            ldsm4(a[0], b0 + (uint32_t)(SM_A + (arow     )*PITCH + ks + acolH)*2);
            ldsm4(a[1], b0 + (uint32_t)(SM_A + (arow + 16)*PITCH + ks + acolH)*2);
            #pragma unroll
            for (int ni = 0; ni < 4; ni++) {
                uint32_t wo = (uint32_t)((brow + ni*8)*PITCH + ks + bcolH)*2;
                ldsm2(bh[ni], b0 + SM_WH*2 + wo);
                ldsm2(bl[ni], b0 + SM_WL*2 + wo);
            }
            #pragma unroll
            for (int mi = 0; mi < 2; mi++)
                #pragma unroll
                for (int ni = 0; ni < 4; ni++) {
                    mma_bf16(acc[mi][ni], a[mi], bh[ni]);
                    mma_bf16(acc[mi][ni], a[mi], bl[ni]);
                }
        }
        if (c + 2 < nch)
            load_chunk(sb + ((c + 2) % 3)*(ST_ELEMS*2), A, Wh, Wl,
                       mBase, nBase, K, (c + 2)*32, tid);
        CP_COMMIT();
    }

    int cr = lane >> 2, cc = (lane & 3) * 2;
    #pragma unroll
    for (int mi = 0; mi < 2; mi++) {
        #pragma unroll
        for (int ni = 0; ni < 4; ni++) {
            int gn = nBase + nw + ni*8 + cc;
            int row0 = mBase + mw + mi*16 + cr;
            if (mode == 3) {
                inproj_pair(row0,     gn, acc[mi][ni][0], acc[mi][ni][1],
                            (__half*)p0, (__half*)p1);
                inproj_pair(row0 + 8, gn, acc[mi][ni][2], acc[mi][ni][3],
                            (__half*)p0, (__half*)p1);
            } else if (mode == 2) {
                float b0v = bias[gn], b1v = bias[gn + 1];
                dtbc_pair(row0,     gn, acc[mi][ni][0] + b0v, acc[mi][ni][1] + b1v, p0, p1);
                dtbc_pair(row0 + 8, gn, acc[mi][ni][2] + b0v, acc[mi][ni][3] + b1v, p0, p1);
            } else {
                if (gn >= Nstore) continue;
                float* pc0 = C + (size_t)row0*ldc + gn;
                float* pc1 = C + (size_t)(row0 + 8)*ldc + gn;
                float2 v0 = make_float2(acc[mi][ni][0], acc[mi][ni][1]);
                float2 v1 = make_float2(acc[mi][ni][2], acc[mi][ni][3]);
                if (mode == 1) {
                    float2 o0 = *(float2*)pc0, o1 = *(float2*)pc1;
                    v0.x += o0.x; v0.y += o0.y; v1.x += o1.x; v1.y += o1.y;
                }
                *(float2*)pc0 = v0;
                *(float2*)pc1 = v1;
            }
        }
    }
}

// ---------------- weight prep: transpose + bf16 hi/lo split ----------------
__global__ void k_tr(const float* __restrict__ src, __nv_bfloat16* __restrict__ dh,
                     __nv_bfloat16* __restrict__ dl, int K, int N,
                     size_t sLayer, size_t dLayer) {
    __shared__ float tile[32][33];
    const float* s = src + blockIdx.z * sLayer;
    size_t doff = blockIdx.z * dLayer;
    int n0 = blockIdx.x * 32, k0 = blockIdx.y * 32;
    int tx = threadIdx.x, ty = threadIdx.y;
    #pragma unroll
    for (int i = 0; i < 4; i++)
        tile[ty + i*8][tx] = s[(size_t)(k0 + ty + i*8)*N + n0 + tx];
    __syncthreads();
    #pragma unroll
    for (int i = 0; i < 4; i++) {
        float v = tile[tx][ty + i*8];
        size_t o = doff + (size_t)(n0 + ty + i*8)*K + k0 + tx;
        __nv_bfloat16 hh = __float2bfloat16(v);
        dh[o] = hh;
        dl[o] = __float2bfloat16(v - __bfloat162float(hh));
    }
}
__global__ void k_prep_bc(const float* __restrict__ WB, const float* __restrict__ WC,
                          const float* __restrict__ bdt,
                          __nv_bfloat16* __restrict__ Wh, __nv_bfloat16* __restrict__ Wl,
                          float* __restrict__ bias) {
    int idx = blockIdx.x * 256 + threadIdx.x;   // 4*512*32
    int l = idx >> 14, r = idx & 16383, k = r >> 5, c = r & 31;
    float v = (c < 16) ? WB[((size_t)l*512 + k)*16 + c]
                       : WC[((size_t)l*512 + k)*16 + (c - 16)];
    size_t o = ((size_t)l*NDTBC + 512 + c)*512 + k;
    __nv_bfloat16 hh = __float2bfloat16(v);
    Wh[o] = hh;
    Wl[o] = __float2bfloat16(v - __bfloat162float(hh));
    if (idx < 4*NDTBC) {
        int ll = idx / NDTBC, n = idx % NDTBC;
        bias[idx] = (n < 512) ? bdt[ll*512 + n] : 0.f;
    }
}

// ---------------- non-GEMM kernels ----------------
__device__ __forceinline__ float blkSum128(float v) {
    __shared__ float sh[4];
    v += __shfl_xor_sync(0xffffffffu, v, 16);
    v += __shfl_xor_sync(0xffffffffu, v, 8);
    v += __shfl_xor_sync(0xffffffffu, v, 4);
    v += __shfl_xor_sync(0xffffffffu, v, 2);
    v += __shfl_xor_sync(0xffffffffu, v, 1);
    __syncthreads();
    if ((threadIdx.x & 31) == 0) sh[threadIdx.x >> 5] = v;
    __syncthreads();
    return sh[0]+sh[1]+sh[2]+sh[3];
}
__device__ __forceinline__ float blkSum256(float v) {
    __shared__ float sh[8];
    v += __shfl_xor_sync(0xffffffffu, v, 16);
    v += __shfl_xor_sync(0xffffffffu, v, 8);
    v += __shfl_xor_sync(0xffffffffu, v, 4);
    v += __shfl_xor_sync(0xffffffffu, v, 2);
    v += __shfl_xor_sync(0xffffffffu, v, 1);
    __syncthreads();
    if ((threadIdx.x & 31) == 0) sh[threadIdx.x >> 5] = v;
    __syncthreads();
    return sh[0]+sh[1]+sh[2]+sh[3]+sh[4]+sh[5]+sh[6]+sh[7];
}
__global__ void k_inproj_ln2(const float* __restrict__ x, const float* __restrict__ w_in,
                             const float* __restrict__ b_in, const float* __restrict__ g0,
                             const float* __restrict__ be0, const float* __restrict__ g1,
                             const float* __restrict__ be1, float* __restrict__ out,
                             __nv_bfloat16* __restrict__ oa) {
    int t = blockIdx.x, d2 = threadIdx.x * 2;
    int b = t >> 10, l = t & 1023;
    const float* xb = x + (size_t)b*4*LL + l;
    float xc[4];
    #pragma unroll
    for (int c = 0; c < 4; c++) xc[c] = xb[c*LL];
    float v0 = b_in[d2], v1 = b_in[d2 + 1];
    #pragma unroll
    for (int c = 0; c < 4; c++) {
        v0 += xc[c] * w_in[d2*4 + c];
        v1 += xc[c] * w_in[(d2+1)*4 + c];
    }
    float mean = blkSum128(v0 + v1) * (1.f/DM);
    float e0 = v0 - mean, e1 = v1 - mean;
    float var = blkSum128(e0*e0 + e1*e1) * (1.f/DM);
    float rs = rsqrtf(var + 1e-5f);
    float u0 = e0*rs*g0[d2] + be0[d2];
    float u1 = e1*rs*g0[d2+1] + be0[d2+1];
    *(float2*)(out + (size_t)t*DM + d2) = make_float2(u0, u1);
    float m2 = blkSum128(u0 + u1) * (1.f/DM);
    float f0 = u0 - m2, f1 = u1 - m2;
    float v2 = blkSum128(f0*f0 + f1*f1) * (1.f/DM);
    float rs2 = rsqrtf(v2 + 1e-5f);
    *(__nv_bfloat162*)(oa + (size_t)t*DM + d2) =
        __floats2bfloat162_rn(f0*rs2*g1[d2] + be1[d2], f1*rs2*g1[d2+1] + be1[d2+1]);
}
__global__ void k_ln_split(const float* __restrict__ src, const float* __restrict__ g,
                           const float* __restrict__ be, __nv_bfloat16* __restrict__ oa) {
    int t = blockIdx.x, d2 = threadIdx.x * 2;
    float2 v = *(const float2*)(src + (size_t)t*DM + d2);
    float mean = blkSum128(v.x + v.y) * (1.f/DM);
    float e0 = v.x - mean, e1 = v.y - mean;
    float var = blkSum128(e0*e0 + e1*e1) * (1.f/DM);
    float rs = rsqrtf(var + 1e-5f);
    *(__nv_bfloat162*)(oa + (size_t)t*DM + d2) =
        __floats2bfloat162_rn(e0*rs*g[d2] + be[d2], e1*rs*g[d2+1] + be[d2+1]);
}
__global__ void k_lnmean(const float* __restrict__ src, const float* __restrict__ g,
                         const float* __restrict__ be, float* __restrict__ out) {
    int t = blockIdx.x, d = threadIdx.x;
    float v = src[(size_t)t*DM + d];
    float mean = blkSum256(v) * (1.f/DM);
    float diff = v - mean;
    float var  = blkSum256(diff*diff) * (1.f/DM);
    float r = diff * rsqrtf(var + 1e-5f) * g[d] + be[d];
    atomicAdd(out + (t >> 10)*DM + d, r * (1.f/LL));
}
// conv + silu, 2 adjacent d per thread; fp16 x in, bf16 a out
__global__ void k_conv(const __half* __restrict__ gx, const __half* __restrict__ szh,
                       const float* __restrict__ cw, const float* __restrict__ cb,
                       const float* __restrict__ Dv,
                       __nv_bfloat16* __restrict__ oa, __half2* __restrict__ szdxz) {
    int idx2 = blockIdx.x * blockDim.x + threadIdx.x;   // over NT*DI/2
    int d2 = (idx2 & (DI/2 - 1)) * 2;
    int t = idx2 >> 8;
    int l = t & (LL - 1);
    size_t base = (size_t)t*DI + d2;
    float acc0 = cb[d2], acc1 = cb[d2 + 1];
    #pragma unroll
    for (int j = 0; j < 4; j++) {
        int ls = l - 3 + j;
        if (ls >= 0) {
            __half2 x2 = *(const __half2*)(gx + base + (size_t)(j - 3)*DI);
            acc0 += __half2float(x2.x) * cw[d2*4 + j];
            acc1 += __half2float(x2.y) * cw[(d2+1)*4 + j];
        }
    }
    float r0 = acc0 / (1.f + __expf(-acc0));
    float r1 = acc1 / (1.f + __expf(-acc1));
    *(__nv_bfloat162*)(oa + base) = __floats2bfloat162_rn(r0, r1);
    __half2 z2 = *(const __half2*)(szh + base);
    float s0 = __half2float(z2.x), s1 = __half2float(z2.y);
    __half2 g0 = __floats2half2_rn(s0, Dv[d2] * r0 * s0);
    __half2 g1 = __floats2half2_rn(s1, Dv[d2+1] * r1 * s1);
    uint2 pk;
    pk.x = *(uint32_t*)&g0;
    pk.y = *(uint32_t*)&g1;
    *(uint2*)(szdxz + base) = pk;
}

// ---------------- selective scan: chunked-parallel (64-token warmup) -------
// record/token (words): dt[0,16) | x bf16 [16,24) | B[24,40) | C[40,56) | g half2 [56,72)
#define SC_TOK 72
#define SC_TILE 64
#define SC_EMIT 256
#define SC_BUF (SC_TILE*SC_TOK)
#define SCAN_SMEM (2*SC_BUF*4)

__device__ __forceinline__ void scan_load_tile(
    uint32_t sdst, int tok0, int dbase, int tid,
    const float* sdt, const __nv_bfloat16* xa, const float* bc, const __half2* szdxz)
{
    int token = tid >> 2, q = tid & 3;
    int t = tok0 + token;
    uint32_t dst = sdst + (uint32_t)(token*SC_TOK)*4;
    size_t o512 = (size_t)t*DI + dbase;
    cp16(dst +       q*16, sdt + o512 + q*4);
    if (q < 2) cp16(dst + 64 + q*16, xa + o512 + q*8);
    cp16(dst +  96 + q*16, bc + (size_t)t*32 + q*4);
    cp16(dst + 160 + q*16, bc + (size_t)t*32 + 16 + q*4);
    cp16(dst + 224 + q*16, szdxz + o512 + q*4);
}

__global__ void __launch_bounds__(256) k_scan(
    const float* __restrict__ sdt, const float* __restrict__ bc,
    const __half2* __restrict__ szdxz, const float* __restrict__ A_log,
    const __nv_bfloat16* __restrict__ xa, __nv_bfloat16* __restrict__ y)
{
    extern __shared__ float sbuf[];
    uint32_t sbase = smem_u32(sbuf);
    int tid = threadIdx.x, warp = tid >> 5, lane = tid & 31;
    int b     = blockIdx.x >> 5;
    int dbase = (blockIdx.x & 31) * 16;
    int chunk = blockIdx.y;
    int half = lane >> 4, s = lane & 15;
    int dloc = warp*2 + half;
    int d = dbase + dloc;
    const int tb = b * LL;

    int emit0 = chunk * SC_EMIT;
    int start = (chunk == 0) ? 0 : emit0 - SC_TILE;
    int warmTiles = (chunk == 0) ? 0 : 1;
    int ntiles = (emit0 + SC_EMIT - start) / SC_TILE;

    float A2 = -__expf(A_log[d*DS + s]) * 1.4426950408889634f;
    float h = 0.f;

    scan_load_tile(sbase, tb + start, dbase, tid, sdt, xa, bc, szdxz);
    CP_COMMIT();
    scan_load_tile(sbase + SC_BUF*4, tb + start + SC_TILE, dbase, tid,
                   sdt, xa, bc, szdxz);
    CP_COMMIT();

    for (int tile = 0; tile < ntiles; tile++) {
        CP_WAIT1();
        __syncthreads();
        const float* buf = sbuf + (tile & 1) * SC_BUF;
        int t0 = tb + start + tile*SC_TILE;
        bool emit = (tile >= warmTiles);
        #pragma unroll 4
        for (int k = 0; k < SC_TILE; k++) {
            const float* rec = buf + k*SC_TOK;
            const __nv_bfloat16* xp = (const __nv_bfloat16*)(rec + 16);
            float dtv = rec[dloc];
            float xv  = __bfloat162float(xp[dloc]);
            float Bv  = rec[24 + s];
            float Cv  = rec[40 + s];
            float Ab = ex2f(A2 * dtv);
            h = Ab * h + (dtv * xv) * Bv;
            float p = h * Cv;
            p += __shfl_xor_sync(0xffffffffu, p, 8);
            p += __shfl_xor_sync(0xffffffffu, p, 4);
            p += __shfl_xor_sync(0xffffffffu, p, 2);
            p += __shfl_xor_sync(0xffffffffu, p, 1);
            if (emit && s == 0) {
                float2 gv = __half22float2(((const __half2*)(rec + 56))[dloc]);
                y[(size_t)(t0 + k)*DI + d] = __float2bfloat16(p * gv.x + gv.y);
            }
        }
        __syncthreads();
        if (tile + 2 < ntiles)
            scan_load_tile(sbase + (tile & 1)*SC_BUF*4,
                           tb + start + (tile + 2)*SC_TILE, dbase, tid,
                           sdt, xa, bc, szdxz);
        CP_COMMIT();
    }
}

__global__ void k_zero(float* __restrict__ out) {
    out[blockIdx.x * DM + threadIdx.x] = 0.f;
}

// ---------------- host ----------------
extern "C" void kernel_launch(void* const* d_in, const int* in_sizes, int n_in,
                              void* d_out, int out_size) {
    const float* x       = (const float*)d_in[0];
    const float* w_in    = (const float*)d_in[1];
    const float* b_in    = (const float*)d_in[2];
    const float* ln_in_g = (const float*)d_in[3];
    const float* ln_in_b = (const float*)d_in[4];
    const float* ln_g    = (const float*)d_in[5];
    const float* ln_b    = (const float*)d_in[6];
    const float* W_inpr  = (const float*)d_in[7];
    const float* conv_w  = (const float*)d_in[8];
    const float* conv_b  = (const float*)d_in[9];
    const float* W_dt    = (const float*)d_in[10];
    const float* b_dt    = (const float*)d_in[11];
    const float* W_B     = (const float*)d_in[12];
    const float* W_C     = (const float*)d_in[13];
    const float* A_log   = (const float*)d_in[14];
    const float* Dv      = (const float*)d_in[15];
    const float* W_out   = (const float*)d_in[16];
    const float* ln_f_g  = (const float*)d_in[17];
    const float* ln_f_b  = (const float*)d_in[18];
    float* out = (float*)d_out;

    float *h, *bias, *bcv, *sdt;
    __half *szh, *gx;
    __half2* szdxz;
    __nv_bfloat16 *ga, *gy;
    __nv_bfloat16 *winh, *winl, *wdth, *wdtl, *wouth, *woutl;
    cudaGetSymbolAddress((void**)&h,     g_h);
    cudaGetSymbolAddress((void**)&bcv,   g_bc);
    cudaGetSymbolAddress((void**)&sdt,   g_sdt);
    cudaGetSymbolAddress((void**)&szh,   g_szh);
    cudaGetSymbolAddress((void**)&szdxz, g_szdxz);
    cudaGetSymbolAddress((void**)&gx,    g_x);
    cudaGetSymbolAddress((void**)&ga,    g_a);
    cudaGetSymbolAddress((void**)&gy,    g_y);
    cudaGetSymbolAddress((void**)&bias,  g_bias);
    cudaGetSymbolAddress((void**)&winh,  g_win_h);
    cudaGetSymbolAddress((void**)&winl,  g_win_l);
    cudaGetSymbolAddress((void**)&wdth,  g_wdt_h);
    cudaGetSymbolAddress((void**)&wdtl,  g_wdt_l);
    cudaGetSymbolAddress((void**)&wouth, g_wout_h);
    cudaGetSymbolAddress((void**)&woutl, g_wout_l);

    cudaFuncSetAttribute(k_tcgemm, cudaFuncAttributeMaxDynamicSharedMemorySize, GEMM_SMEM);
    cudaFuncSetAttribute(k_scan,   cudaFuncAttributeMaxDynamicSharedMemorySize, SCAN_SMEM);

    dim3 trb(32, 8);
    k_tr<<<dim3(32, 8, 4), trb>>>(W_inpr, winh, winl, 256, 1024,                 // 0
                                  (size_t)256*1024, (size_t)1024*256);
    k_tr<<<dim3(16, 16, 4), trb>>>(W_dt, wdth, wdtl, 512, 512,                   // 1
                                   (size_t)512*512, (size_t)NDTBC*512);
    k_inproj_ln2<<<NT, 128>>>(x, w_in, b_in, ln_in_g, ln_in_b,                   // 2
                              ln_g, ln_b, h, ga);
    k_tcgemm<<<dim3(16, 64), 256, GEMM_SMEM>>>(                                  // 3 <- prof
        ga, winh, winl, nullptr, nullptr, 256, 0, 0, 3, (float*)gx, (float*)szh);
    k_prep_bc<<<(4*512*32)/256, 256>>>(W_B, W_C, b_dt, wdth, wdtl, bias);
    k_tr<<<dim3(8, 16, 4), trb>>>(W_out, wouth, woutl, 512, 256,
                                  (size_t)512*256, (size_t)256*512);

    for (int i = 0; i < 4; i++) {
        if (i > 0) {
            k_ln_split<<<NT, 128>>>(h, ln_g + i*DM, ln_b + i*DM, ga);
            k_tcgemm<<<dim3(16, 64), 256, GEMM_SMEM>>>(
                ga, winh + (size_t)i*1024*256, winl + (size_t)i*1024*256,
                nullptr, nullptr, 256, 0, 0, 3, (float*)gx, (float*)szh);
        }
        k_conv<<<(NT*DI/2)/256, 256>>>(gx, szh, conv_w + i*DI*4, conv_b + i*DI,
                                       Dv + i*DI, ga, szdxz);
        k_tcgemm<<<dim3(NDTBC/64, 64), 256, GEMM_SMEM>>>(
            ga, wdth + (size_t)i*NDTBC*512, wdtl + (size_t)i*NDTBC*512,
            bias + i*NDTBC, nullptr, 512, 0, 0, 2, sdt, bcv);
        k_scan<<<dim3(BB*(DI/16), LL/SC_EMIT), 256, SCAN_SMEM>>>(
            sdt, bcv, szdxz, A_log + i*DI*DS, ga, gy);
        k_tcgemm<<<dim3(4, 64), 256, GEMM_SMEM>>>(
            gy, wouth + (size_t)i*256*512, woutl + (size_t)i*256*512,
            nullptr, h, 512, 256, 256, 1, nullptr, nullptr);
    }

    k_zero<<<BB, DM>>>(out);
    k_lnmean<<<NT, 256>>>(h, ln_f_g, ln_f_b, out);
}

// round 16
// speedup vs baseline: 1.6821x; 1.0560x over previous
#include <cuda_runtime.h>
#include <cuda_bf16.h>
#include <cuda_fp16.h>
#include <cstdint>

#define BB 8
#define LL 1024
#define DM 256
#define DI 512
#define DS 16
#define NT (BB*LL)   // 8192 tokens
#define NDTBC 576    // 512 dt + 16 B + 16 C + 32 pad
#define NTDI ((size_t)NT*DI)

// ---------------- scratch (device globals: allocation-free) ----------------
__device__ float g_h [NT*DM];
__device__ float g_bc[NT*32];        // B|C per token (fp32)
__device__ float g_sdt[NT*DI];       // softplus(dt_pre)
__device__ __half g_szh[NT*DI];      // silu(z) fp16 (inproj epilogue)
__device__ __half2 g_szdxz[NT*DI];   // (silu(z), D*x*silu(z)) packed
__device__ __half g_x [NT*DI];       // pre-conv x (inproj epilogue, conv input only)
__device__ __nv_bfloat16 g_a [NT*DI];   // GEMM A: LN out (256-stride) / conv out (512)
__device__ __nv_bfloat16 g_y [NT*DI];   // scan out (GEMM A for out-proj)
__device__ __nv_bfloat16 g_win_h [4*1024*256];
__device__ __nv_bfloat16 g_win_l [4*1024*256];
__device__ __nv_bfloat16 g_wdt_h [4*NDTBC*512];   // rows 544..575 stay zero
__device__ __nv_bfloat16 g_wdt_l [4*NDTBC*512];
__device__ __nv_bfloat16 g_wout_h[4*256*512];
__device__ __nv_bfloat16 g_wout_l[4*256*512];
__device__ float g_bias[4*NDTBC];

// ---------------- helpers ----------------
__device__ __forceinline__ uint32_t smem_u32(const void* p) {
    uint32_t a;
    asm("{ .reg .u64 t; cvta.to.shared.u64 t, %1; cvt.u32.u64 %0, t; }" : "=r"(a) : "l"(p));
    return a;
}
__device__ __forceinline__ void ldsm4(uint32_t* r, uint32_t addr) {
    asm volatile("ldmatrix.sync.aligned.m8n8.x4.shared.b16 {%0,%1,%2,%3}, [%4];"
                 : "=r"(r[0]), "=r"(r[1]), "=r"(r[2]), "=r"(r[3]) : "r"(addr));
}
__device__ __forceinline__ void mma_bf16(float* c, const uint32_t* a, const uint32_t* b) {
    asm volatile("mma.sync.aligned.m16n8k16.row.col.f32.bf16.bf16.f32 "
        "{%0,%1,%2,%3}, {%4,%5,%6,%7}, {%8,%9}, {%0,%1,%2,%3};"
        : "+f"(c[0]), "+f"(c[1]), "+f"(c[2]), "+f"(c[3])
        : "r"(a[0]), "r"(a[1]), "r"(a[2]), "r"(a[3]), "r"(b[0]), "r"(b[1]));
}
__device__ __forceinline__ void cp16(uint32_t dst, const void* src) {
    asm volatile("cp.async.cg.shared.global [%0], [%1], 16;" :: "r"(dst), "l"(src));
}
#define CP_COMMIT() asm volatile("cp.async.commit_group;" ::: "memory")
#define CP_WAIT1()  asm volatile("cp.async.wait_group 1;" ::: "memory")
__device__ __forceinline__ float ex2f(float x) {
    float r; asm("ex2.approx.f32 %0, %1;" : "=f"(r) : "f"(x)); return r;
}

#define PITCH 40   // bf16 elems per smem row (80B), BK=32, conflict-free ldmatrix
#define ST_ELEMS ((128 + 64 + 64) * PITCH)   // 10240 elems / stage
#define SM_A  0
#define SM_WH (128*PITCH)
#define SM_WL (192*PITCH)
#define GEMM_SMEM (3*ST_ELEMS*2)             // 61440 B -> 3 CTAs/SM

// ---------------- tensor-core GEMM: CTA tile 128x64, warp tile 32x32 -------
// A single bf16 [M][K]; W bf16 hi/lo [Npad][K]. 2-term: A*Wh + A*Wl.
// modes: 0 = store C, 1 = accumulate into C, 2 = dtbc epilogue,
//        3 = inproj epilogue (x -> fp16, z -> silu fp16)
__device__ __forceinline__ void load_chunk(
    uint32_t base, const __nv_bfloat16* A,
    const __nv_bfloat16* Wh, const __nv_bfloat16* Wl,
    int mBase, int nBase, int K, int k0, int tid)
{
    #pragma unroll
    for (int i = 0; i < 2; i++) {
        int idx = tid + i*256;                 // 0..511: 128 rows x 4 segs
        int row = idx >> 2, seg = (idx & 3) << 3;
        size_t go = (size_t)(mBase + row)*K + k0 + seg;
        cp16(base + SM_A*2 + (uint32_t)(row*PITCH + seg)*2, A + go);
    }
    {
        int row = tid >> 2, seg = (tid & 3) << 3;  // 64 rows x 4 segs
        size_t go = (size_t)(nBase + row)*K + k0 + seg;
        uint32_t so = (uint32_t)(row*PITCH + seg)*2;
        cp16(base + SM_WH*2 + so, Wh + go);
        cp16(base + SM_WL*2 + so, Wl + go);
    }
}

__device__ __forceinline__ void dtbc_pair(int t, int gn, float v0, float v1,
                                          float* sdt, float* bc) {
    if (gn < 512) {
        float d0 = (v0 > 20.f) ? v0 : __logf(1.f + __expf(v0));
        float d1 = (v1 > 20.f) ? v1 : __logf(1.f + __expf(v1));
        *(float2*)(sdt + (size_t)t*DI + gn) = make_float2(d0, d1);
    } else if (gn < 544) {
        *(float2*)(bc + (size_t)t*32 + (gn - 512)) = make_float2(v0, v1);
    }
}
__device__ __forceinline__ void inproj_pair(int t, int gn, float v0, float v1,
                                            __half* gx, __half* szh) {
    if (gn < 512) {
        *(__half2*)(gx + (size_t)t*DI + gn) = __floats2half2_rn(v0, v1);
    } else {
        float s0 = v0 / (1.f + __expf(-v0));
        float s1 = v1 / (1.f + __expf(-v1));
        *(__half2*)(szh + (size_t)t*DI + (gn - 512)) = __floats2half2_rn(s0, s1);
    }
}

__global__ void __launch_bounds__(256, 3) k_tcgemm(
    const __nv_bfloat16* __restrict__ A,
    const __nv_bfloat16* __restrict__ Wh, const __nv_bfloat16* __restrict__ Wl,
    const float* __restrict__ bias, float* __restrict__ C,
    int K, int ldc, int Nstore, int mode,
    float* __restrict__ p0, float* __restrict__ p1)
{
    extern __shared__ __nv_bfloat16 smem[];
    uint32_t sb = smem_u32(smem);

    int tid = threadIdx.x, lane = tid & 31, warp = tid >> 5;
    int mBase = blockIdx.y * 128, nBase = blockIdx.x * 64;
    int mw = (warp & 3) * 32;
    int nw = (warp >> 2) * 32;

    float acc[2][4][4];
    #pragma unroll
    for (int i = 0; i < 2; i++)
        #pragma unroll
        for (int j = 0; j < 4; j++)
            #pragma unroll
            for (int k = 0; k < 4; k++) acc[i][j][k] = 0.f;

    int arow = mw + (lane & 15);
    int acolH = (lane >> 4) << 3;
    // W ldsm4 lane mapping: groups of 8 lanes -> tiles {n0-7,k0-7},{n0-7,k8-15},{n8-15,k0-7},{n8-15,k8-15}
    int wrow = nw + ((lane >> 4) << 3) + (lane & 7);
    int wcolH = ((lane >> 3) & 1) << 3;

    int nch = K >> 5;
    load_chunk(sb, A, Wh, Wl, mBase, nBase, K, 0, tid);
    CP_COMMIT();
    load_chunk(sb + ST_ELEMS*2, A, Wh, Wl, mBase, nBase, K, 32, tid);
    CP_COMMIT();

    for (int c = 0; c < nch; c++) {
        CP_WAIT1();
        __syncthreads();
        uint32_t b0 = sb + (c % 3)*(ST_ELEMS*2);
        #pragma unroll
        for (int ks = 0; ks < 32; ks += 16) {
            uint32_t a[2][4], bh2[2][4], bl2[2][4];
            ldsm4(a[0], b0 + (uint32_t)(SM_A + (arow     )*PITCH + ks + acolH)*2);
            ldsm4(a[1], b0 + (uint32_t)(SM_A + (arow + 16)*PITCH + ks + acolH)*2);
            #pragma unroll
            for (int ni2 = 0; ni2 < 2; ni2++) {
                uint32_t wo = (uint32_t)((wrow + ni2*16)*PITCH + ks + wcolH)*2;
                ldsm4(bh2[ni2], b0 + SM_WH*2 + wo);
                ldsm4(bl2[ni2], b0 + SM_WL*2 + wo);
            }
            #pragma unroll
            for (int mi = 0; mi < 2; mi++)
                #pragma unroll
                for (int ni = 0; ni < 4; ni++) {
                    mma_bf16(acc[mi][ni], a[mi], &bh2[ni >> 1][(ni & 1)*2]);
                    mma_bf16(acc[mi][ni], a[mi], &bl2[ni >> 1][(ni & 1)*2]);
                }
        }
        if (c + 2 < nch)
            load_chunk(sb + ((c + 2) % 3)*(ST_ELEMS*2), A, Wh, Wl,
                       mBase, nBase, K, (c + 2)*32, tid);
        CP_COMMIT();
    }

    int cr = lane >> 2, cc = (lane & 3) * 2;
    #pragma unroll
    for (int mi = 0; mi < 2; mi++) {
        #pragma unroll
        for (int ni = 0; ni < 4; ni++) {
            int gn = nBase + nw + ni*8 + cc;
            int row0 = mBase + mw + mi*16 + cr;
            if (mode == 3) {
                inproj_pair(row0,     gn, acc[mi][ni][0], acc[mi][ni][1],
                            (__half*)p0, (__half*)p1);
                inproj_pair(row0 + 8, gn, acc[mi][ni][2], acc[mi][ni][3],
                            (__half*)p0, (__half*)p1);
            } else if (mode == 2) {
                float b0v = bias[gn], b1v = bias[gn + 1];
                dtbc_pair(row0,     gn, acc[mi][ni][0] + b0v, acc[mi][ni][1] + b1v, p0, p1);
                dtbc_pair(row0 + 8, gn, acc[mi][ni][2] + b0v, acc[mi][ni][3] + b1v, p0, p1);
            } else {
                if (gn >= Nstore) continue;
                float* pc0 = C + (size_t)row0*ldc + gn;
                float* pc1 = C + (size_t)(row0 + 8)*ldc + gn;
                float2 v0 = make_float2(acc[mi][ni][0], acc[mi][ni][1]);
                float2 v1 = make_float2(acc[mi][ni][2], acc[mi][ni][3]);
                if (mode == 1) {
                    float2 o0 = *(float2*)pc0, o1 = *(float2*)pc1;
                    v0.x += o0.x; v0.y += o0.y; v1.x += o1.x; v1.y += o1.y;
                }
                *(float2*)pc0 = v0;
                *(float2*)pc1 = v1;
            }
        }
    }
}

// ---------------- weight prep: transpose + bf16 hi/lo split ----------------
__global__ void k_tr(const float* __restrict__ src, __nv_bfloat16* __restrict__ dh,
                     __nv_bfloat16* __restrict__ dl, int K, int N,
                     size_t sLayer, size_t dLayer) {
    __shared__ float tile[32][33];
    const float* s = src + blockIdx.z * sLayer;
    size_t doff = blockIdx.z * dLayer;
    int n0 = blockIdx.x * 32, k0 = blockIdx.y * 32;
    int tx = threadIdx.x, ty = threadIdx.y;
    #pragma unroll
    for (int i = 0; i < 4; i++)
        tile[ty + i*8][tx] = s[(size_t)(k0 + ty + i*8)*N + n0 + tx];
    __syncthreads();
    #pragma unroll
    for (int i = 0; i < 4; i++) {
        float v = tile[tx][ty + i*8];
        size_t o = doff + (size_t)(n0 + ty + i*8)*K + k0 + tx;
        __nv_bfloat16 hh = __float2bfloat16(v);
        dh[o] = hh;
        dl[o] = __float2bfloat16(v - __bfloat162float(hh));
    }
}
__global__ void k_prep_bc(const float* __restrict__ WB, const float* __restrict__ WC,
                          const float* __restrict__ bdt,
                          __nv_bfloat16* __restrict__ Wh, __nv_bfloat16* __restrict__ Wl,
                          float* __restrict__ bias) {
    int idx = blockIdx.x * 256 + threadIdx.x;   // 4*512*32
    int l = idx >> 14, r = idx & 16383, k = r >> 5, c = r & 31;
    float v = (c < 16) ? WB[((size_t)l*512 + k)*16 + c]
                       : WC[((size_t)l*512 + k)*16 + (c - 16)];
    size_t o = ((size_t)l*NDTBC + 512 + c)*512 + k;
    __nv_bfloat16 hh = __float2bfloat16(v);
    Wh[o] = hh;
    Wl[o] = __float2bfloat16(v - __bfloat162float(hh));
    if (idx < 4*NDTBC) {
        int ll = idx / NDTBC, n = idx % NDTBC;
        bias[idx] = (n < 512) ? bdt[ll*512 + n] : 0.f;
    }
}

// ---------------- non-GEMM kernels ----------------
__device__ __forceinline__ float blkSum128(float v) {
    __shared__ float sh[4];
    v += __shfl_xor_sync(0xffffffffu, v, 16);
    v += __shfl_xor_sync(0xffffffffu, v, 8);
    v += __shfl_xor_sync(0xffffffffu, v, 4);
    v += __shfl_xor_sync(0xffffffffu, v, 2);
    v += __shfl_xor_sync(0xffffffffu, v, 1);
    __syncthreads();
    if ((threadIdx.x & 31) == 0) sh[threadIdx.x >> 5] = v;
    __syncthreads();
    return sh[0]+sh[1]+sh[2]+sh[3];
}
__device__ __forceinline__ float blkSum256(float v) {
    __shared__ float sh[8];
    v += __shfl_xor_sync(0xffffffffu, v, 16);
    v += __shfl_xor_sync(0xffffffffu, v, 8);
    v += __shfl_xor_sync(0xffffffffu, v, 4);
    v += __shfl_xor_sync(0xffffffffu, v, 2);
    v += __shfl_xor_sync(0xffffffffu, v, 1);
    __syncthreads();
    if ((threadIdx.x & 31) == 0) sh[threadIdx.x >> 5] = v;
    __syncthreads();
    return sh[0]+sh[1]+sh[2]+sh[3]+sh[4]+sh[5]+sh[6]+sh[7];
}
__global__ void k_inproj_ln2(const float* __restrict__ x, const float* __restrict__ w_in,
                             const float* __restrict__ b_in, const float* __restrict__ g0,
                             const float* __restrict__ be0, const float* __restrict__ g1,
                             const float* __restrict__ be1, float* __restrict__ out,
                             __nv_bfloat16* __restrict__ oa) {
    int t = blockIdx.x, d2 = threadIdx.x * 2;
    int b = t >> 10, l = t & 1023;
    const float* xb = x + (size_t)b*4*LL + l;
    float xc[4];
    #pragma unroll
    for (int c = 0; c < 4; c++) xc[c] = xb[c*LL];
    float v0 = b_in[d2], v1 = b_in[d2 + 1];
    #pragma unroll
    for (int c = 0; c < 4; c++) {
        v0 += xc[c] * w_in[d2*4 + c];
        v1 += xc[c] * w_in[(d2+1)*4 + c];
    }
    float mean = blkSum128(v0 + v1) * (1.f/DM);
    float e0 = v0 - mean, e1 = v1 - mean;
    float var = blkSum128(e0*e0 + e1*e1) * (1.f/DM);
    float rs = rsqrtf(var + 1e-5f);
    float u0 = e0*rs*g0[d2] + be0[d2];
    float u1 = e1*rs*g0[d2+1] + be0[d2+1];
    *(float2*)(out + (size_t)t*DM + d2) = make_float2(u0, u1);
    float m2 = blkSum128(u0 + u1) * (1.f/DM);
    float f0 = u0 - m2, f1 = u1 - m2;
    float v2 = blkSum128(f0*f0 + f1*f1) * (1.f/DM);
    float rs2 = rsqrtf(v2 + 1e-5f);
    *(__nv_bfloat162*)(oa + (size_t)t*DM + d2) =
        __floats2bfloat162_rn(f0*rs2*g1[d2] + be1[d2], f1*rs2*g1[d2+1] + be1[d2+1]);
}
__global__ void k_ln_split(const float* __restrict__ src, const float* __restrict__ g,
                           const float* __restrict__ be, __nv_bfloat16* __restrict__ oa) {
    int t = blockIdx.x, d2 = threadIdx.x * 2;
    float2 v = *(const float2*)(src + (size_t)t*DM + d2);
    float mean = blkSum128(v.x + v.y) * (1.f/DM);
    float e0 = v.x - mean, e1 = v.y - mean;
    float var = blkSum128(e0*e0 + e1*e1) * (1.f/DM);
    float rs = rsqrtf(var + 1e-5f);
    *(__nv_bfloat162*)(oa + (size_t)t*DM + d2) =
        __floats2bfloat162_rn(e0*rs*g[d2] + be[d2], e1*rs*g[d2+1] + be[d2+1]);
}
__global__ void k_lnmean(const float* __restrict__ src, const float* __restrict__ g,
                         const float* __restrict__ be, float* __restrict__ out) {
    int t = blockIdx.x, d = threadIdx.x;
    float v = src[(size_t)t*DM + d];
    float mean = blkSum256(v) * (1.f/DM);
    float diff = v - mean;
    float var  = blkSum256(diff*diff) * (1.f/DM);
    float r = diff * rsqrtf(var + 1e-5f) * g[d] + be[d];
    atomicAdd(out + (t >> 10)*DM + d, r * (1.f/LL));
}
// conv + silu, 2 adjacent d per thread; fp16 x in, bf16 a out
__global__ void k_conv(const __half* __restrict__ gx, const __half* __restrict__ szh,
                       const float* __restrict__ cw, const float* __restrict__ cb,
                       const float* __restrict__ Dv,
                       __nv_bfloat16* __restrict__ oa, __half2* __restrict__ szdxz) {
    int idx2 = blockIdx.x * blockDim.x + threadIdx.x;   // over NT*DI/2
    int d2 = (idx2 & (DI/2 - 1)) * 2;
    int t = idx2 >> 8;
    int l = t & (LL - 1);
    size_t base = (size_t)t*DI + d2;
    float acc0 = cb[d2], acc1 = cb[d2 + 1];
    #pragma unroll
    for (int j = 0; j < 4; j++) {
        int ls = l - 3 + j;
        if (ls >= 0) {
            __half2 x2 = *(const __half2*)(gx + base + (size_t)(j - 3)*DI);
            acc0 += __half2float(x2.x) * cw[d2*4 + j];
            acc1 += __half2float(x2.y) * cw[(d2+1)*4 + j];
        }
    }
    float r0 = acc0 / (1.f + __expf(-acc0));
    float r1 = acc1 / (1.f + __expf(-acc1));
    *(__nv_bfloat162*)(oa + base) = __floats2bfloat162_rn(r0, r1);
    __half2 z2 = *(const __half2*)(szh + base);
    float s0 = __half2float(z2.x), s1 = __half2float(z2.y);
    __half2 g0 = __floats2half2_rn(s0, Dv[d2] * r0 * s0);
    __half2 g1 = __floats2half2_rn(s1, Dv[d2+1] * r1 * s1);
    uint2 pk;
    pk.x = *(uint32_t*)&g0;
    pk.y = *(uint32_t*)&g1;
    *(uint2*)(szdxz + base) = pk;
}

// ---------------- selective scan: chunked + 4 states/thread ----------------
// Block = 64 threads = 2 warps, 16 d of one batch. Warp covers 8 d x 4 sg.
// record/token (words): dt[0,16) | x bf16 [16,24) | B[24,40) | C[40,56) | g half2 [56,72)
#define SC_TOK 72
#define SC_TILE 64
#define SC_EMIT 256
#define SC_BUF (SC_TILE*SC_TOK)
#define SCAN_SMEM (2*SC_BUF*4)

__device__ __forceinline__ void scan_load_tile(
    uint32_t sdst, int tok0, int dbase, int tid,
    const float* sdt, const __nv_bfloat16* xa, const float* bc, const __half2* szdxz)
{
    int t = tok0 + tid;                       // thread-per-token (64 threads)
    uint32_t dst = sdst + (uint32_t)tid*SC_TOK*4;
    size_t o = (size_t)t*DI + dbase;
    cp16(dst +   0, sdt + o);
    cp16(dst +  16, sdt + o + 4);
    cp16(dst +  32, sdt + o + 8);
    cp16(dst +  48, sdt + o + 12);
    cp16(dst +  64, xa + o);
    cp16(dst +  80, xa + o + 8);
    const float* bt = bc + (size_t)t*32;
    cp16(dst +  96, bt);
    cp16(dst + 112, bt + 4);
    cp16(dst + 128, bt + 8);
    cp16(dst + 144, bt + 12);
    cp16(dst + 160, bt + 16);
    cp16(dst + 176, bt + 20);
    cp16(dst + 192, bt + 24);
    cp16(dst + 208, bt + 28);
    cp16(dst + 224, szdxz + o);
    cp16(dst + 240, szdxz + o + 4);
    cp16(dst + 256, szdxz + o + 8);
    cp16(dst + 272, szdxz + o + 12);
}

__global__ void __launch_bounds__(64) k_scan(
    const float* __restrict__ sdt, const float* __restrict__ bc,
    const __half2* __restrict__ szdxz, const float* __restrict__ A_log,
    const __nv_bfloat16* __restrict__ xa, __nv_bfloat16* __restrict__ y)
{
    extern __shared__ float sbuf[];
    uint32_t sbase = smem_u32(sbuf);
    int tid = threadIdx.x, warp = tid >> 5, lane = tid & 31;
    int b     = blockIdx.x >> 5;
    int dbase = (blockIdx.x & 31) * 16;
    int chunk = blockIdx.y;
    int dloc = warp*8 + (lane >> 2);   // 0..15
    int sg   = lane & 3;               // states sg*4 .. sg*4+3
    int d = dbase + dloc;
    const int tb = b * LL;

    int emit0 = chunk * SC_EMIT;
    int start = (chunk == 0) ? 0 : emit0 - SC_TILE;
    int warmTiles = (chunk == 0) ? 0 : 1;
    int ntiles = (emit0 + SC_EMIT - start) / SC_TILE;

    float A2[4];
    #pragma unroll
    for (int j = 0; j < 4; j++)
        A2[j] = -__expf(A_log[d*DS + sg*4 + j]) * 1.4426950408889634f;
    float hs[4] = {0.f, 0.f, 0.f, 0.f};

    scan_load_tile(sbase, tb + start, dbase, tid, sdt, xa, bc, szdxz);
    CP_COMMIT();
    scan_load_tile(sbase + SC_BUF*4, tb + start + SC_TILE, dbase, tid,
                   sdt, xa, bc, szdxz);
    CP_COMMIT();

    for (int tile = 0; tile < ntiles; tile++) {
        CP_WAIT1();
        __syncthreads();
        const float* buf = sbuf + (tile & 1) * SC_BUF;
        int t0 = tb + start + tile*SC_TILE;
        bool emit = (tile >= warmTiles);
        #pragma unroll 4
        for (int k = 0; k < SC_TILE; k++) {
            const float* rec = buf + k*SC_TOK;
            const __nv_bfloat16* xp = (const __nv_bfloat16*)(rec + 16);
            float dtv = rec[dloc];
            float xv  = __bfloat162float(xp[dloc]);
            float4 Bv = ((const float4*)(rec + 24))[sg];
            float4 Cv = ((const float4*)(rec + 40))[sg];
            float u = dtv * xv;
            hs[0] = ex2f(A2[0]*dtv) * hs[0] + u * Bv.x;
            hs[1] = ex2f(A2[1]*dtv) * hs[1] + u * Bv.y;
            hs[2] = ex2f(A2[2]*dtv) * hs[2] + u * Bv.z;
            hs[3] = ex2f(A2[3]*dtv) * hs[3] + u * Bv.w;
            float p = hs[0]*Cv.x + hs[1]*Cv.y + hs[2]*Cv.z + hs[3]*Cv.w;
            p += __shfl_xor_sync(0xffffffffu, p, 1);
            p += __shfl_xor_sync(0xffffffffu, p, 2);
            if (emit && sg == 0) {
                float2 gv = __half22float2(((const __half2*)(rec + 56))[dloc]);
                y[(size_t)(t0 + k)*DI + d] = __float2bfloat16(p * gv.x + gv.y);
            }
        }
        __syncthreads();
        if (tile + 2 < ntiles)
            scan_load_tile(sbase + (tile & 1)*SC_BUF*4,
                           tb + start + (tile + 2)*SC_TILE, dbase, tid,
                           sdt, xa, bc, szdxz);
        CP_COMMIT();
    }
}

__global__ void k_zero(float* __restrict__ out) {
    out[blockIdx.x * DM + threadIdx.x] = 0.f;
}

// ---------------- host ----------------
extern "C" void kernel_launch(void* const* d_in, const int* in_sizes, int n_in,
                              void* d_out, int out_size) {
    const float* x       = (const float*)d_in[0];
    const float* w_in    = (const float*)d_in[1];
    const float* b_in    = (const float*)d_in[2];
    const float* ln_in_g = (const float*)d_in[3];
    const float* ln_in_b = (const float*)d_in[4];
    const float* ln_g    = (const float*)d_in[5];
    const float* ln_b    = (const float*)d_in[6];
    const float* W_inpr  = (const float*)d_in[7];
    const float* conv_w  = (const float*)d_in[8];
    const float* conv_b  = (const float*)d_in[9];
    const float* W_dt    = (const float*)d_in[10];
    const float* b_dt    = (const float*)d_in[11];
    const float* W_B     = (const float*)d_in[12];
    const float* W_C     = (const float*)d_in[13];
    const float* A_log   = (const float*)d_in[14];
    const float* Dv      = (const float*)d_in[15];
    const float* W_out   = (const float*)d_in[16];
    const float* ln_f_g  = (const float*)d_in[17];
    const float* ln_f_b  = (const float*)d_in[18];
    float* out = (float*)d_out;

    float *h, *bias, *bcv, *sdt;
    __half *szh, *gx;
    __half2* szdxz;
    __nv_bfloat16 *ga, *gy;
    __nv_bfloat16 *winh, *winl, *wdth, *wdtl, *wouth, *woutl;
    cudaGetSymbolAddress((void**)&h,     g_h);
    cudaGetSymbolAddress((void**)&bcv,   g_bc);
    cudaGetSymbolAddress((void**)&sdt,   g_sdt);
    cudaGetSymbolAddress((void**)&szh,   g_szh);
    cudaGetSymbolAddress((void**)&szdxz, g_szdxz);
    cudaGetSymbolAddress((void**)&gx,    g_x);
    cudaGetSymbolAddress((void**)&ga,    g_a);
    cudaGetSymbolAddress((void**)&gy,    g_y);
    cudaGetSymbolAddress((void**)&bias,  g_bias);
    cudaGetSymbolAddress((void**)&winh,  g_win_h);
    cudaGetSymbolAddress((void**)&winl,  g_win_l);
    cudaGetSymbolAddress((void**)&wdth,  g_wdt_h);
    cudaGetSymbolAddress((void**)&wdtl,  g_wdt_l);
    cudaGetSymbolAddress((void**)&wouth, g_wout_h);
    cudaGetSymbolAddress((void**)&woutl, g_wout_l);

    cudaFuncSetAttribute(k_tcgemm, cudaFuncAttributeMaxDynamicSharedMemorySize, GEMM_SMEM);
    cudaFuncSetAttribute(k_scan,   cudaFuncAttributeMaxDynamicSharedMemorySize, SCAN_SMEM);

    dim3 trb(32, 8);
    k_tr<<<dim3(32, 8, 4), trb>>>(W_inpr, winh, winl, 256, 1024,                 // 0
                                  (size_t)256*1024, (size_t)1024*256);
    k_tr<<<dim3(16, 16, 4), trb>>>(W_dt, wdth, wdtl, 512, 512,                   // 1
                                   (size_t)512*512, (size_t)NDTBC*512);
    k_inproj_ln2<<<NT, 128>>>(x, w_in, b_in, ln_in_g, ln_in_b,                   // 2
                              ln_g, ln_b, h, ga);
    k_tcgemm<<<dim3(16, 64), 256, GEMM_SMEM>>>(                                  // 3 <- prof
        ga, winh, winl, nullptr, nullptr, 256, 0, 0, 3, (float*)gx, (float*)szh);
    k_prep_bc<<<(4*512*32)/256, 256>>>(W_B, W_C, b_dt, wdth, wdtl, bias);
    k_tr<<<dim3(8, 16, 4), trb>>>(W_out, wouth, woutl, 512, 256,
                                  (size_t)512*256, (size_t)256*512);

    for (int i = 0; i < 4; i++) {
        if (i > 0) {
            k_ln_split<<<NT, 128>>>(h, ln_g + i*DM, ln_b + i*DM, ga);
            k_tcgemm<<<dim3(16, 64), 256, GEMM_SMEM>>>(
                ga, winh + (size_t)i*1024*256, winl + (size_t)i*1024*256,
                nullptr, nullptr, 256, 0, 0, 3, (float*)gx, (float*)szh);
        }
        k_conv<<<(NT*DI/2)/256, 256>>>(gx, szh, conv_w + i*DI*4, conv_b + i*DI,
                                       Dv + i*DI, ga, szdxz);
        k_tcgemm<<<dim3(NDTBC/64, 64), 256, GEMM_SMEM>>>(
            ga, wdth + (size_t)i*NDTBC*512, wdtl + (size_t)i*NDTBC*512,
            bias + i*NDTBC, nullptr, 512, 0, 0, 2, sdt, bcv);
        k_scan<<<dim3(BB*32, LL/SC_EMIT), 64, SCAN_SMEM>>>(
            sdt, bcv, szdxz, A_log + i*DI*DS, ga, gy);
        k_tcgemm<<<dim3(4, 64), 256, GEMM_SMEM>>>(
            gy, wouth + (size_t)i*256*512, woutl + (size_t)i*256*512,
            nullptr, h, 512, 256, 256, 1, nullptr, nullptr);
    }

    k_zero<<<BB, DM>>>(out);
    k_lnmean<<<NT, 256>>>(h, ln_f_g, ln_f_b, out);
}